// round 6
// baseline (speedup 1.0000x reference)
#include <cuda_runtime.h>
#include <cuda_bf16.h>
#include <math.h>

#define T     1024
#define HDIM  1024
#define NEXP  16
#define IDIM  512
#define ISDIM 2048
#define TOPK  4
#define SST   20          // smem row stride in floats

// ---------------- scratch --------------------------------------------------
__device__ int   g_counts[NEXP];
__device__ int   g_tok[NEXP * T];
__device__ float g_wt[NEXP * T];
__device__ int   g_slot[T * TOPK];
__device__ float g_sg[T];
__device__ float g_act[(size_t)NEXP * T * IDIM];
__device__ float g_acts[(size_t)T * ISDIM];
__device__ float g_down[(size_t)NEXP * T * HDIM];

// ---------------- helpers --------------------------------------------------
__device__ __forceinline__ float to_tf32(float x) {
    unsigned u;
    asm("cvt.rna.tf32.f32 %0, %1;" : "=r"(u) : "f"(x));
    return __uint_as_float(u);
}
__device__ __forceinline__ float4 cvt4(float4 v) {
    v.x = to_tf32(v.x); v.y = to_tf32(v.y);
    v.z = to_tf32(v.z); v.w = to_tf32(v.w);
    return v;
}
__device__ __forceinline__ unsigned smem_u32(const void* p) {
    return (unsigned)__cvta_generic_to_shared(p);
}
__device__ __forceinline__ void ldsm4(unsigned* d, unsigned addr) {
    asm volatile("ldmatrix.sync.aligned.m8n8.x4.shared.b16 {%0,%1,%2,%3}, [%4];"
                 : "=r"(d[0]), "=r"(d[1]), "=r"(d[2]), "=r"(d[3]) : "r"(addr));
}
__device__ __forceinline__ void mma_tf32(float* d, const unsigned* a, const unsigned* b) {
    asm volatile(
        "mma.sync.aligned.m16n8k8.row.col.f32.tf32.tf32.f32 "
        "{%0,%1,%2,%3}, {%4,%5,%6,%7}, {%8,%9}, {%0,%1,%2,%3};\n"
        : "+f"(d[0]), "+f"(d[1]), "+f"(d[2]), "+f"(d[3])
        : "r"(a[0]), "r"(a[1]), "r"(a[2]), "r"(a[3]), "r"(b[0]), "r"(b[1]));
}
__device__ __forceinline__ float silu(float g) { return g / (1.f + expf(-g)); }

// ---------------- kernel 0 + 1: counts & router -----------------------------
__global__ void zero_counts_kernel() {
    if (threadIdx.x < NEXP) g_counts[threadIdx.x] = 0;
}

__global__ void router_kernel(const float* __restrict__ x,
                              const float* __restrict__ wr,
                              const float* __restrict__ wsg,
                              float* __restrict__ logits_out) {
    int t    = blockIdx.x;
    int warp = threadIdx.x >> 5;
    int lane = threadIdx.x & 31;
    __shared__ float s_logit[NEXP];

    const float* xr = x + (size_t)t * HDIM;
    {
        float acc = 0.f;
        for (int h = lane; h < HDIM; h += 32)
            acc += xr[h] * wr[h * NEXP + warp];
        #pragma unroll
        for (int o = 16; o; o >>= 1) acc += __shfl_xor_sync(0xffffffffu, acc, o);
        if (lane == 0) { s_logit[warp] = acc; logits_out[t * NEXP + warp] = acc; }
    }
    if (warp == 0) {
        float acc = 0.f;
        for (int h = lane; h < HDIM; h += 32) acc += xr[h] * wsg[h];
        #pragma unroll
        for (int o = 16; o; o >>= 1) acc += __shfl_xor_sync(0xffffffffu, acc, o);
        if (lane == 0) g_sg[t] = 1.f / (1.f + expf(-acc));
    }
    __syncthreads();

    if (threadIdx.x == 0) {
        float p[NEXP];
        float mx = -1e30f;
        #pragma unroll
        for (int e = 0; e < NEXP; e++) mx = fmaxf(mx, s_logit[e]);
        float sum = 0.f;
        #pragma unroll
        for (int e = 0; e < NEXP; e++) { p[e] = expf(s_logit[e] - mx); sum += p[e]; }
        float inv = 1.f / sum;
        #pragma unroll
        for (int e = 0; e < NEXP; e++) p[e] *= inv;

        int idx[TOPK]; float w[TOPK]; float wsum = 0.f;
        #pragma unroll
        for (int k = 0; k < TOPK; k++) {
            int best = 0; float bv = -1.f;
            #pragma unroll
            for (int e = 0; e < NEXP; e++)
                if (p[e] > bv) { bv = p[e]; best = e; }
            idx[k] = best; w[k] = bv; wsum += bv; p[best] = -2.f;
        }
        float winv = 1.f / wsum;
        #pragma unroll
        for (int k = 0; k < TOPK; k++) {
            int e = idx[k];
            int pos = atomicAdd(&g_counts[e], 1);
            g_tok[e * T + pos] = t;
            g_wt[e * T + pos]  = w[k] * winv;
            g_slot[t * TOPK + k] = e * T + pos;
        }
    }
}

// ============================================================================
// Fused launch 1: gate/up GEMMs (expert + shared). BM=64,BN=64,BK=16, 128 thr.
// ============================================================================
#define GU_SMEM_FLOATS (3 * 2 * 64 * SST)     // 7680 floats = 30720 B

__device__ __forceinline__
void gateup_body(float* sm, const float* __restrict__ Bgp,
                 const float* __restrict__ Bup, int ldb,
                 const float* arow0, bool aval, int count_lim, int m0, int n0,
                 float* __restrict__ Cout, int ldc, bool expert_mode) {
    float* As  = sm;
    float* Btg = sm + 2 * 64 * SST;
    float* Btu = sm + 4 * 64 * SST;

    int tid = threadIdx.x, lane = tid & 31, warp = tid >> 5;
    int wm = (warp >> 1) * 32, wn = (warp & 1) * 32;
    int r = lane >> 2, c = lane & 3;

    int aoff = (wm + (lane & 7) + ((lane >> 3) & 1) * 8) * SST + ((lane >> 4) & 1) * 4;
    unsigned aA0 = smem_u32(As) + (unsigned)aoff * 4;
    int boff0 = (wn + (lane & 7) + ((lane >> 4) & 1) * 8) * SST + ((lane >> 3) & 1) * 4;
    unsigned aBg0 = smem_u32(Btg) + (unsigned)boff0 * 4;
    unsigned aBu0 = smem_u32(Btu) + (unsigned)boff0 * 4;
    const unsigned BUFB = 64 * SST * 4;

    int arl = tid & 63, akf = (tid >> 6) * 8;
    int bnl = tid & 63, bkf = (tid >> 6) * 8;

    // stepped pointers (per-j offsets are constant immediates)
    const float* pA  = arow0 + akf;
    const float* pBg = Bgp + (size_t)bkf * ldb + n0 + bnl;
    const float* pBu = Bup + (size_t)bkf * ldb + n0 + bnl;

    float4 pa0, pa1;
    float pg[8], pu[8];

    #define GUF_LD() do {                                                      \
        pa0 = *(const float4*)pA;                                              \
        pa1 = *(const float4*)(pA + 4);                                        \
        _Pragma("unroll")                                                      \
        for (int j = 0; j < 8; j++) {                                          \
            pg[j] = pBg[(size_t)j * ldb];                                      \
            pu[j] = pBu[(size_t)j * ldb];                                      \
        }                                                                      \
        pA += 16; pBg += (size_t)16 * ldb; pBu += (size_t)16 * ldb;            \
    } while (0)
    #define GUF_ST(B) do {                                                     \
        *(float4*)&As[(B) * 64 * SST + arl * SST + akf]     = cvt4(pa0);       \
        *(float4*)&As[(B) * 64 * SST + arl * SST + akf + 4] = cvt4(pa1);       \
        *(float4*)&Btg[(B) * 64 * SST + bnl * SST + bkf]                       \
            = cvt4(make_float4(pg[0], pg[1], pg[2], pg[3]));                   \
        *(float4*)&Btg[(B) * 64 * SST + bnl * SST + bkf + 4]                   \
            = cvt4(make_float4(pg[4], pg[5], pg[6], pg[7]));                   \
        *(float4*)&Btu[(B) * 64 * SST + bnl * SST + bkf]                       \
            = cvt4(make_float4(pu[0], pu[1], pu[2], pu[3]));                   \
        *(float4*)&Btu[(B) * 64 * SST + bnl * SST + bkf + 4]                   \
            = cvt4(make_float4(pu[4], pu[5], pu[6], pu[7]));                   \
    } while (0)

    float ag[2][4][4] = {};
    float au[2][4][4] = {};

    GUF_LD(); GUF_ST(0);
    const int NTILES = HDIM / 16;
    for (int kt = 0; kt < NTILES; kt++) {
        __syncthreads();
        if (kt + 1 < NTILES) GUF_LD();
        unsigned bsel = (kt & 1) * BUFB;
        #pragma unroll
        for (int kb = 0; kb < 2; kb++) {
            unsigned koff = bsel + kb * 32;
            unsigned af[2][4], bgf[2][4], buf_[2][4];
            ldsm4(af[0], aA0 + koff);
            ldsm4(af[1], aA0 + koff + 16 * SST * 4);
            ldsm4(bgf[0], aBg0 + koff);
            ldsm4(bgf[1], aBg0 + koff + 16 * SST * 4);
            ldsm4(buf_[0], aBu0 + koff);
            ldsm4(buf_[1], aBu0 + koff + 16 * SST * 4);
            #pragma unroll
            for (int nt = 0; nt < 4; nt++) {
                const unsigned* bg = &bgf[nt >> 1][(nt & 1) * 2];
                const unsigned* bu = &buf_[nt >> 1][(nt & 1) * 2];
                #pragma unroll
                for (int mt = 0; mt < 2; mt++) {
                    mma_tf32(ag[mt][nt], af[mt], bg);
                    mma_tf32(au[mt][nt], af[mt], bu);
                }
            }
        }
        if (kt + 1 < NTILES) GUF_ST((kt + 1) & 1);
    }
    (void)aval;

    #pragma unroll
    for (int mt = 0; mt < 2; mt++) {
        int row0 = m0 + wm + mt * 16 + r;
        #pragma unroll
        for (int nt = 0; nt < 4; nt++) {
            int col = n0 + wn + nt * 8 + c * 2;
            if (row0 < count_lim) {
                float2 o = { silu(ag[mt][nt][0]) * au[mt][nt][0],
                             silu(ag[mt][nt][1]) * au[mt][nt][1] };
                *(float2*)(Cout + (size_t)row0 * ldc + col) = o;
            }
            if (row0 + 8 < count_lim) {
                float2 o = { silu(ag[mt][nt][2]) * au[mt][nt][2],
                             silu(ag[mt][nt][3]) * au[mt][nt][3] };
                *(float2*)(Cout + (size_t)(row0 + 8) * ldc + col) = o;
            }
        }
    }
}

__global__ __launch_bounds__(128)
void fused_gateup(const float* __restrict__ x,
                  const float* __restrict__ wg,
                  const float* __restrict__ wu,
                  const float* __restrict__ wsg,
                  const float* __restrict__ wsu) {
    __shared__ __align__(16) float sm[GU_SMEM_FLOATS];
    int bid = blockIdx.x;
    int tid = threadIdx.x;
    if (bid < 2048) {
        int e  = bid >> 7;
        int by = (bid >> 3) & 15;
        int bx = bid & 7;
        int count = g_counts[e];
        int m0 = by * 64;
        if (m0 >= count) return;
        int arl = tid & 63;
        int row = m0 + arl;
        // gathered A row; out-of-range rows point at token 0 (garbage rows are
        // never stored because the epilogue is count-guarded)
        int tok = (row < count) ? g_tok[e * T + row] : 0;
        const float* arow0 = x + (size_t)tok * HDIM;
        gateup_body(sm, wg + (size_t)e * HDIM * IDIM, wu + (size_t)e * HDIM * IDIM,
                    IDIM, arow0, row < count, count, m0, bx * 64,
                    g_act + (size_t)e * T * IDIM, IDIM, true);
    } else {
        int s  = bid - 2048;
        int bx = s & 31;
        int by = s >> 5;
        int m0 = by * 64;
        const float* arow0 = x + (size_t)(m0 + (tid & 63)) * HDIM;
        gateup_body(sm, wsg, wsu, ISDIM, arow0, true, T, m0, bx * 64,
                    g_acts, ISDIM, false);
    }
}

// ============================================================================
// Fused launch 2: down GEMMs. BM=64, BN=128, BK=16, 128 thr, warp 32x64.
// Expert path scales by routing weight into g_down; shared path writes
// sg * (acts @ wsd) into out (expert slots added by combine_add_kernel).
// ============================================================================
#define DN_SMEM_FLOATS (2 * 64 * SST + 2 * 128 * SST)   // 7680 floats = 30720 B

struct DnAcc { float a[2][8][4]; };

__device__ __forceinline__
void down_mainloop(float* sm, const float* __restrict__ arow0,
                   const float* __restrict__ Bp, int kdim, int n0, DnAcc& A) {
    float* As = sm;
    float* Bt = sm + 2 * 64 * SST;

    int tid = threadIdx.x, lane = tid & 31, warp = tid >> 5;
    int wm = (warp >> 1) * 32, wn = (warp & 1) * 64;

    int aoff = (wm + (lane & 7) + ((lane >> 3) & 1) * 8) * SST + ((lane >> 4) & 1) * 4;
    unsigned aA0 = smem_u32(As) + (unsigned)aoff * 4;
    int boff0 = (wn + (lane & 7) + ((lane >> 4) & 1) * 8) * SST + ((lane >> 3) & 1) * 4;
    unsigned aB0 = smem_u32(Bt) + (unsigned)boff0 * 4;
    const unsigned ABUF = 64 * SST * 4, BBUF = 128 * SST * 4;

    int arl = tid & 63, akf = (tid >> 6) * 8;
    int bnl = tid;

    const float* pA = arow0 + akf;
    const float* pB = Bp + n0 + bnl;

    float4 pa0, pa1;
    float pb[16];

    #define DNF_LD() do {                                                      \
        pa0 = *(const float4*)pA;                                              \
        pa1 = *(const float4*)(pA + 4);                                        \
        _Pragma("unroll")                                                      \
        for (int j = 0; j < 16; j++) pb[j] = pB[(size_t)j * HDIM];             \
        pA += 16; pB += (size_t)16 * HDIM;                                     \
    } while (0)
    #define DNF_ST(BUF) do {                                                   \
        *(float4*)&As[(BUF) * 64 * SST + arl * SST + akf]     = cvt4(pa0);     \
        *(float4*)&As[(BUF) * 64 * SST + arl * SST + akf + 4] = cvt4(pa1);     \
        _Pragma("unroll")                                                      \
        for (int q = 0; q < 4; q++)                                            \
            *(float4*)&Bt[(BUF) * 128 * SST + bnl * SST + q * 4] =             \
                cvt4(make_float4(pb[q*4], pb[q*4+1], pb[q*4+2], pb[q*4+3]));   \
    } while (0)

    DNF_LD(); DNF_ST(0);
    const int NTILES = kdim / 16;
    for (int kt = 0; kt < NTILES; kt++) {
        __syncthreads();
        if (kt + 1 < NTILES) DNF_LD();
        unsigned bselA = (kt & 1) * ABUF, bselB = (kt & 1) * BBUF;
        #pragma unroll
        for (int kb = 0; kb < 2; kb++) {
            unsigned af[2][4], bf[4][4];
            ldsm4(af[0], aA0 + bselA + kb * 32);
            ldsm4(af[1], aA0 + bselA + kb * 32 + 16 * SST * 4);
            #pragma unroll
            for (int p = 0; p < 4; p++)
                ldsm4(bf[p], aB0 + bselB + kb * 32 + p * 16 * SST * 4);
            #pragma unroll
            for (int nt = 0; nt < 8; nt++) {
                const unsigned* b = &bf[nt >> 1][(nt & 1) * 2];
                #pragma unroll
                for (int mt = 0; mt < 2; mt++)
                    mma_tf32(A.a[mt][nt], af[mt], b);
            }
        }
        if (kt + 1 < NTILES) DNF_ST((kt + 1) & 1);
    }
}

__global__ __launch_bounds__(128)
void fused_down(const float* __restrict__ wd,
                const float* __restrict__ wsd,
                float* __restrict__ out) {
    __shared__ __align__(16) float sm[DN_SMEM_FLOATS];
    int bid = blockIdx.x;
    int tid = threadIdx.x, lane = tid & 31, warp = tid >> 5;
    int wm = (warp >> 1) * 32, wn = (warp & 1) * 64;
    int r = lane >> 2, c = lane & 3;

    DnAcc A = {};

    if (bid < 2048) {
        int e  = bid >> 7;
        int by = (bid >> 3) & 15;
        int bx = bid & 7;
        int count = g_counts[e];
        int m0 = by * 64;
        if (m0 >= count) return;
        int n0 = bx * 128;

        const float* arow0 = g_act + (size_t)e * T * IDIM
                           + (size_t)(m0 + (tid & 63)) * IDIM;
        down_mainloop(sm, arow0, wd + (size_t)e * IDIM * HDIM, IDIM, n0, A);

        #pragma unroll
        for (int mt = 0; mt < 2; mt++) {
            int row0 = m0 + wm + mt * 16 + r;
            float w0 = (row0 < count)     ? g_wt[e * T + row0]     : 0.f;
            float w1 = (row0 + 8 < count) ? g_wt[e * T + row0 + 8] : 0.f;
            #pragma unroll
            for (int nt = 0; nt < 8; nt++) {
                int col = n0 + wn + nt * 8 + c * 2;
                if (row0 < count) {
                    float2 o = { w0 * A.a[mt][nt][0], w0 * A.a[mt][nt][1] };
                    *(float2*)(g_down + (size_t)(e * T + row0) * HDIM + col) = o;
                }
                if (row0 + 8 < count) {
                    float2 o = { w1 * A.a[mt][nt][2], w1 * A.a[mt][nt][3] };
                    *(float2*)(g_down + (size_t)(e * T + row0 + 8) * HDIM + col) = o;
                }
            }
        }
    } else {
        int s  = bid - 2048;
        int by = s >> 3;
        int bx = s & 7;
        int m0 = by * 64;
        int n0 = bx * 128;

        const float* arow0 = g_acts + (size_t)(m0 + (tid & 63)) * ISDIM;
        down_mainloop(sm, arow0, wsd, ISDIM, n0, A);

        #pragma unroll
        for (int mt = 0; mt < 2; mt++) {
            #pragma unroll
            for (int half = 0; half < 2; half++) {
                int t = m0 + wm + mt * 16 + r + half * 8;
                float sg = g_sg[t];
                #pragma unroll
                for (int nt = 0; nt < 8; nt++) {
                    int col = n0 + wn + nt * 8 + c * 2;
                    float2 o = { sg * A.a[mt][nt][half * 2 + 0],
                                 sg * A.a[mt][nt][half * 2 + 1] };
                    *(float2*)(out + (size_t)t * HDIM + col) = o;
                }
            }
        }
    }
}

// ---------------- kernel: add gathered expert slots into out ----------------
__global__ __launch_bounds__(256)
void combine_add_kernel(float* __restrict__ out) {
    int i = blockIdx.x * 256 + threadIdx.x;       // over T*HDIM/4 float4s
    int t  = i >> 8;
    int c4 = (i & 255) * 4;
    float* po = out + (size_t)t * HDIM + c4;
    float4 o = *(float4*)po;
    #pragma unroll
    for (int k = 0; k < TOPK; k++) {
        int s = g_slot[t * TOPK + k];
        float4 d = *(const float4*)(g_down + (size_t)s * HDIM + c4);
        o.x += d.x; o.y += d.y; o.z += d.z; o.w += d.w;
    }
    *(float4*)po = o;
}

// ---------------- launch ----------------------------------------------------
extern "C" void kernel_launch(void* const* d_in, const int* in_sizes, int n_in,
                              void* d_out, int out_size) {
    const float* x    = (const float*)d_in[0];
    const float* wr   = (const float*)d_in[1];
    const float* wg   = (const float*)d_in[2];
    const float* wu   = (const float*)d_in[3];
    const float* wd   = (const float*)d_in[4];
    const float* wsg  = (const float*)d_in[5];
    const float* wsu  = (const float*)d_in[6];
    const float* wsd  = (const float*)d_in[7];
    const float* wshg = (const float*)d_in[8];
    float* out = (float*)d_out;

    zero_counts_kernel<<<1, 32>>>();
    router_kernel<<<T, 512>>>(x, wr, wshg, out + (size_t)T * HDIM);
    fused_gateup<<<2048 + 512, 128>>>(x, wg, wu, wsg, wsu);
    fused_down<<<2048 + 128, 128>>>(wd, wsd, out);
    combine_add_kernel<<<(T * HDIM / 4) / 256, 256>>>(out);
}